// round 16
// baseline (speedup 1.0000x reference)
#include <cuda_runtime.h>
#include <cuda_bf16.h>
#include <cuda_fp16.h>
#include <cstdint>
#include <math.h>

#define B_   4
#define LQ_  1024
#define LKV_ 4096
#define D_   512
#define H_   4
#define HD_  128
#define SCALE_ 0.08838834764831845f      // 1/sqrt(128)
#define LOG2E_ 1.4426950408889634f
#define QSCALE_ (SCALE_ * LOG2E_)        // logits emitted in log2 domain

// ---------------------------------------------------------------------------
// Helpers
// ---------------------------------------------------------------------------
__device__ __forceinline__ uint32_t smem_u32(const void* p) {
    uint32_t a;
    asm("{ .reg .u64 t; cvta.to.shared.u64 t, %1; cvt.u32.u64 %0, t; }" : "=r"(a) : "l"(p));
    return a;
}

#define CP_ASYNC16(sa, g) \
    asm volatile("cp.async.cg.shared.global [%0], [%1], 16;" :: "r"(sa), "l"(g))
#define CP_COMMIT() asm volatile("cp.async.commit_group;" ::: "memory")
#define CP_WAIT(n)  asm volatile("cp.async.wait_group %0;" :: "n"(n) : "memory")

__device__ __forceinline__ void ldsm4(uint32_t* r, uint32_t a) {
    asm volatile("ldmatrix.sync.aligned.m8n8.x4.shared.b16 {%0,%1,%2,%3}, [%4];"
                 : "=r"(r[0]), "=r"(r[1]), "=r"(r[2]), "=r"(r[3]) : "r"(a));
}
__device__ __forceinline__ void mma_f16(float* c, const uint32_t* a, const uint32_t* b) {
    asm volatile("mma.sync.aligned.m16n8k16.row.col.f32.f16.f16.f32 "
                 "{%0,%1,%2,%3}, {%4,%5,%6,%7}, {%8,%9}, {%0,%1,%2,%3};"
                 : "+f"(c[0]), "+f"(c[1]), "+f"(c[2]), "+f"(c[3])
                 : "r"(a[0]), "r"(a[1]), "r"(a[2]), "r"(a[3]), "r"(b[0]), "r"(b[1]));
}
__device__ __forceinline__ uint32_t pack_h2(float a, float b) {
    __half2 v = __floats2half2_rn(a, b);
    return *(uint32_t*)&v;
}

// 128B-row swizzle (8 granules of 16B per row), conflict-free for ldsm
#define SWR(r, g) ((uint32_t)(r) * 128 + ((uint32_t)((g) ^ ((r) & 7)) << 4))
// 256B-row swizzle (flash Q/K tiles)
#define SWQ(r, g) ((uint32_t)(r) * 256 + ((uint32_t)((g) ^ ((r) & 15)) << 4))

// ---------------------------------------------------------------------------
// Device scratch (allocation-free)
// ---------------------------------------------------------------------------
#define NX  ((size_t)B_ * LQ_ * D_)
#define NE  ((size_t)B_ * LKV_ * D_)
#define NW  ((size_t)D_ * D_)

__device__ __half g_xh[NX];
__device__ __half g_eh[NE];
__device__ __half g_wqhi[NW], g_wqlo[NW];
__device__ __half g_wk[NW];
__device__ __half g_wv[NW];
__device__ __half g_wohi[NW], g_wolo[NW];
__device__ __half g_qh[NX];
__device__ __half g_kh[NE];
__device__ __half g_vth[NE];           // transposed [b][h*HD+d][lkv]
__device__ __half g_ct[NX];

// ---------------------------------------------------------------------------
// Single prep kernel: y selects task
// ---------------------------------------------------------------------------
__global__ __launch_bounds__(256) void prep_kernel(
    const float* __restrict__ x, const float* __restrict__ enc,
    const float* __restrict__ Wq, const float* __restrict__ Wk,
    const float* __restrict__ Wv, const float* __restrict__ Wo,
    __half* __restrict__ xh, __half* __restrict__ eh,
    __half* __restrict__ wqh, __half* __restrict__ wql,
    __half* __restrict__ wk, __half* __restrict__ wv,
    __half* __restrict__ woh, __half* __restrict__ wol)
{
    const int which = blockIdx.y;
    const int stride = gridDim.x * blockDim.x;
    const int tid0 = blockIdx.x * blockDim.x + threadIdx.x;
    if (which <= 1 || which == 3 || which == 4) {
        const float* in = (which == 0) ? x : (which == 1) ? enc : (which == 3) ? Wk : Wv;
        __half* outp    = (which == 0) ? xh : (which == 1) ? eh : (which == 3) ? wk : wv;
        const int n4    = (which == 0) ? (int)(NX / 4) : (which == 1) ? (int)(NE / 4) : (int)(NW / 4);
        for (int i = tid0; i < n4; i += stride) {
            float4 v = ((const float4*)in)[i];
            ((uint2*)outp)[i] = make_uint2(pack_h2(v.x, v.y), pack_h2(v.z, v.w));
        }
    } else {
        const float* in = (which == 2) ? Wq : Wo;
        __half* hi = (which == 2) ? wqh : woh;
        __half* lo = (which == 2) ? wql : wol;
        const int n4 = (int)(NW / 4);
        for (int i = tid0; i < n4; i += stride) {
            float4 v = ((const float4*)in)[i];
            float f[4] = {v.x, v.y, v.z, v.w};
            float h[4], l[4];
#pragma unroll
            for (int j = 0; j < 4; j++) {
                h[j] = __half2float(__float2half_rn(f[j]));
                l[j] = f[j] - h[j];
            }
            ((uint2*)hi)[i] = make_uint2(pack_h2(h[0], h[1]), pack_h2(h[2], h[3]));
            ((uint2*)lo)[i] = make_uint2(pack_h2(l[0], l[1]), pack_h2(l[2], l[3]));
        }
    }
}

// ---------------------------------------------------------------------------
// Fused K+V projection: ONE CTA computes both K and V outputs for the same
// (m, n) tile, sharing the A (enc) tile in smem. 1-pass fp16, CTA tile
// 128x128, warp tile 64x32 per output, K-chunk 64, 2-stage double buffer.
// 128 MMAs per warp between barriers (flash-density).
// ---------------------------------------------------------------------------
#define KVF_A   0
#define KVF_BK  16384
#define KVF_BV  32768
#define KVF_STG 49152
#define KVF_SMEM (2 * KVF_STG)   // 98304

__global__ __launch_bounds__(256) void kvf_kernel(
    const __half* __restrict__ A,
    const __half* __restrict__ Wk_, const __half* __restrict__ Wv_,
    __half* __restrict__ kh, __half* __restrict__ vth,
    const float* __restrict__ bk, const float* __restrict__ bv)
{
    extern __shared__ char smem[];
    const uint32_t sb = smem_u32(smem);
    const int t = threadIdx.x, wid = t >> 5, lid = t & 31;
    const int wm = wid & 1, wn = wid >> 1;
    const int m0 = blockIdx.y * 128, n0 = blockIdx.x * 128;

    const __half* Ab  = A + (size_t)m0 * D_;
    const __half* Bkb = Wk_ + (size_t)n0 * D_;
    const __half* Bvb = Wv_ + (size_t)n0 * D_;

    float accK[4][4][4], accV[4][4][4];
#pragma unroll
    for (int i = 0; i < 4; i++)
#pragma unroll
        for (int j = 0; j < 4; j++)
#pragma unroll
            for (int r = 0; r < 4; r++) { accK[i][j][r] = 0.f; accV[i][j][r] = 0.f; }

    const int nch = D_ >> 6;

    auto load_stage = [&](int c) {
        const int k0 = c << 6;
        const uint32_t sbase = sb + (c & 1) * KVF_STG;
#pragma unroll
        for (int i = 0; i < 4; i++) {
            int idx = t + i * 256;
            int r = idx >> 3, s = idx & 7;
            uint32_t so = SWR(r, s);
            size_t off = (size_t)r * D_ + k0 + s * 8;
            CP_ASYNC16(sbase + KVF_A + so,  Ab + off);
            CP_ASYNC16(sbase + KVF_BK + so, Bkb + off);
            CP_ASYNC16(sbase + KVF_BV + so, Bvb + off);
        }
        CP_COMMIT();
    };

    load_stage(0);

    for (int c = 0; c < nch; c++) {
        if (c + 1 < nch) { load_stage(c + 1); CP_WAIT(1); }
        else             { CP_WAIT(0); }
        __syncthreads();

        const uint32_t sbase = sb + (c & 1) * KVF_STG;
#pragma unroll
        for (int ks = 0; ks < 4; ks++) {
            uint32_t ah[4][4], bK[2][4], bV[2][4];
            const int ar = wm * 64 + (lid & 15);
            const int ag = ks * 2 + (lid >> 4);
#pragma unroll
            for (int im = 0; im < 4; im++)
                ldsm4(ah[im], sbase + KVF_A + SWR(ar + im * 16, ag));
            const int br = wn * 32 + (lid & 7) + ((lid >> 4) & 1) * 8;
            const int bg = ks * 2 + ((lid >> 3) & 1);
#pragma unroll
            for (int g = 0; g < 2; g++) {
                uint32_t off = SWR(br + g * 16, bg);
                ldsm4(bK[g], sbase + KVF_BK + off);
                ldsm4(bV[g], sbase + KVF_BV + off);
            }
#pragma unroll
            for (int im = 0; im < 4; im++)
#pragma unroll
                for (int in = 0; in < 4; in++) {
                    int g = in >> 1, s2 = (in & 1) * 2;
                    mma_f16(accK[im][in], ah[im], &bK[g][s2]);
                    mma_f16(accV[im][in], ah[im], &bV[g][s2]);
                }
        }
        __syncthreads();   // 2-stage WAR guard
    }

    const int group = lid >> 2, tid4 = lid & 3;

#pragma unroll
    for (int im = 0; im < 4; im++)
#pragma unroll
        for (int in = 0; in < 4; in++) {
            int row = m0 + wm * 64 + im * 16 + group;
            int col = n0 + wn * 32 + in * 8 + tid4 * 2;
#pragma unroll
            for (int rr = 0; rr < 2; rr++) {
                int m = row + rr * 8;
                int bb = m >> 12, kv = m & (LKV_ - 1);
#pragma unroll
                for (int cc = 0; cc < 2; cc++) {
                    int n = col + cc;
                    float vk = accK[im][in][rr * 2 + cc] + bk[n];
                    float vv = accV[im][in][rr * 2 + cc] + bv[n];
                    kh[(size_t)m * D_ + n] = __float2half_rn(vk);
                    vth[((size_t)(bb * D_ + n)) * LKV_ + kv] = __float2half_rn(vv);
                }
            }
        }
}

// ---------------------------------------------------------------------------
// Q / O projection: 2-pass fp16, CTA tile 128x64 (-> 256 CTAs), warp 64x16.
// K-chunk 64, 2-stage double buffer. MODE 0: fp32 out (+bias). MODE 1: fp16
// out ((v+bias)*scale).  (R14-proven)
// ---------------------------------------------------------------------------
#define QO_A   0
#define QO_BH  16384
#define QO_BL  24576
#define QO_STG 32768
#define QO_SMEM 65536

template <int MODE>
__global__ __launch_bounds__(256) void qo_kernel(
    const __half* __restrict__ A,
    const __half* __restrict__ Bh, const __half* __restrict__ Bl,
    float* __restrict__ Cf, __half* __restrict__ Ch,
    const float* __restrict__ bias, float scale)
{
    extern __shared__ char smem[];
    const uint32_t sb = smem_u32(smem);
    const int t = threadIdx.x, wid = t >> 5, lid = t & 31;
    const int wm = wid & 1, wn = wid >> 1;
    const int m0 = blockIdx.y * 128, n0 = blockIdx.x * 64;

    const __half* Ab  = A  + (size_t)m0 * D_;
    const __half* Bbh = Bh + (size_t)n0 * D_;
    const __half* Bbl = Bl + (size_t)n0 * D_;

    float acc[4][2][4];
#pragma unroll
    for (int i = 0; i < 4; i++)
#pragma unroll
        for (int j = 0; j < 2; j++)
#pragma unroll
            for (int r = 0; r < 4; r++) acc[i][j][r] = 0.f;

    const int nch = D_ >> 6;

    auto load_stage = [&](int c) {
        const int k0 = c << 6;
        const uint32_t sbase = sb + (c & 1) * QO_STG;
#pragma unroll
        for (int i = 0; i < 4; i++) {
            int idx = t + i * 256;
            int r = idx >> 3, s = idx & 7;
            CP_ASYNC16(sbase + QO_A + SWR(r, s), Ab + (size_t)r * D_ + k0 + s * 8);
        }
#pragma unroll
        for (int i = 0; i < 2; i++) {
            int idx = t + i * 256;
            int r = idx >> 3, s = idx & 7;
            size_t ob = (size_t)r * D_ + k0 + s * 8;
            uint32_t so = SWR(r, s);
            CP_ASYNC16(sbase + QO_BH + so, Bbh + ob);
            CP_ASYNC16(sbase + QO_BL + so, Bbl + ob);
        }
        CP_COMMIT();
    };

    load_stage(0);

    for (int c = 0; c < nch; c++) {
        if (c + 1 < nch) { load_stage(c + 1); CP_WAIT(1); }
        else             { CP_WAIT(0); }
        __syncthreads();

        const uint32_t sbase = sb + (c & 1) * QO_STG;
#pragma unroll
        for (int ks = 0; ks < 4; ks++) {
            uint32_t ah[4][4], bh[4], bl[4];
            const int ar = wm * 64 + (lid & 15);
            const int ag = ks * 2 + (lid >> 4);
#pragma unroll
            for (int im = 0; im < 4; im++)
                ldsm4(ah[im], sbase + QO_A + SWR(ar + im * 16, ag));
            const int br = wn * 16 + (lid & 7) + ((lid >> 4) & 1) * 8;
            const int bg = ks * 2 + ((lid >> 3) & 1);
            uint32_t off = SWR(br, bg);
            ldsm4(bh, sbase + QO_BH + off);
            ldsm4(bl, sbase + QO_BL + off);
#pragma unroll
            for (int im = 0; im < 4; im++)
#pragma unroll
                for (int in = 0; in < 2; in++) {
                    mma_f16(acc[im][in], ah[im], &bh[in * 2]);
                    mma_f16(acc[im][in], ah[im], &bl[in * 2]);
                }
        }
        __syncthreads();
    }

    const int group = lid >> 2, tid4 = lid & 3;
#pragma unroll
    for (int im = 0; im < 4; im++)
#pragma unroll
        for (int in = 0; in < 2; in++) {
            int row = m0 + wm * 64 + im * 16 + group;
            int col = n0 + wn * 16 + in * 8 + tid4 * 2;
#pragma unroll
            for (int rr = 0; rr < 2; rr++) {
#pragma unroll
                for (int cc = 0; cc < 2; cc++) {
                    float v = acc[im][in][rr * 2 + cc] + bias[col + cc];
                    if (MODE == 0) {
                        Cf[(size_t)(row + rr * 8) * D_ + col + cc] = v;
                    } else {
                        Ch[(size_t)(row + rr * 8) * D_ + col + cc] = __float2half_rn(v * scale);
                    }
                }
            }
        }
}

// ---------------------------------------------------------------------------
// Flash attention (R11/R14-proven): fp16 single-pass, exp2 softmax,
// Q-tile 64, 128 threads, 3-stage KV ring, single barrier per iteration.
// ---------------------------------------------------------------------------
#define F_Q    0
#define F_ST   16384
#define F_STSZ 32768
#define F_K    0
#define F_V    16384
#define FLASH_SMEM (F_ST + 3 * F_STSZ)   // 114688

__global__ __launch_bounds__(128, 2) void flash_kernel(
    const __half* __restrict__ q, const __half* __restrict__ k,
    const __half* __restrict__ vt, __half* __restrict__ ct)
{
    extern __shared__ char smem[];
    const uint32_t sb = smem_u32(smem);
    const int t = threadIdx.x, wid = t >> 5, lid = t & 31;
    const int z = blockIdx.y, zb = z >> 2, zh = z & 3;
    const int q0 = blockIdx.x * 64;

#pragma unroll
    for (int i = 0; i < 8; i++) {
        int idx = t + i * 128;
        int r = idx >> 4, g = idx & 15;
        const __half* gp = q + ((size_t)(zb * LQ_ + q0 + r)) * D_ + zh * HD_ + g * 8;
        CP_ASYNC16(sb + F_Q + SWQ(r, g), gp);
    }
    CP_COMMIT();

    auto load_kv = [&](int kt2) {
        const int kv0 = kt2 * 64;
        const uint32_t stb = sb + F_ST + (kt2 % 3) * F_STSZ;
#pragma unroll
        for (int i = 0; i < 8; i++) {
            int idx = t + i * 128;
            int r = idx >> 4, g = idx & 15;
            const __half* gp = k + ((size_t)(zb * LKV_ + kv0 + r)) * D_ + zh * HD_ + g * 8;
            CP_ASYNC16(stb + F_K + SWQ(r, g), gp);
        }
#pragma unroll
        for (int i = 0; i < 8; i++) {
            int idx = t + i * 128;
            int r = idx >> 3, g = idx & 7;
            const __half* gp = vt + ((size_t)(zb * D_ + zh * HD_ + r)) * LKV_ + kv0 + g * 8;
            CP_ASYNC16(stb + F_V + SWR(r, g), gp);
        }
        CP_COMMIT();
    };

    load_kv(0);

    float oacc[16][4];
#pragma unroll
    for (int i = 0; i < 16; i++)
#pragma unroll
        for (int j = 0; j < 4; j++) oacc[i][j] = 0.f;
    float mr0 = -1e30f, mr1 = -1e30f, l0 = 0.f, l1 = 0.f;

    for (int kt = 0; kt < LKV_ / 64; kt++) {
        if (kt + 1 < LKV_ / 64) { load_kv(kt + 1); CP_WAIT(1); }
        else                    { CP_WAIT(0); }
        __syncthreads();
        const uint32_t stb = sb + F_ST + (kt % 3) * F_STSZ;

        float sacc[8][4];
#pragma unroll
        for (int i = 0; i < 8; i++)
#pragma unroll
            for (int j = 0; j < 4; j++) sacc[i][j] = 0.f;

#pragma unroll
        for (int ks = 0; ks < 8; ks++) {
            uint32_t aq[4];
            const int ar = wid * 16 + (lid & 15);
            const int ag = ks * 2 + (lid >> 4);
            ldsm4(aq, sb + F_Q + SWQ(ar, ag));
#pragma unroll
            for (int jn = 0; jn < 4; jn++) {
                uint32_t bk4[4];
                const int br = jn * 16 + (lid & 7) + ((lid >> 4) & 1) * 8;
                const int bg = ks * 2 + ((lid >> 3) & 1);
                ldsm4(bk4, stb + F_K + SWQ(br, bg));
                mma_f16(sacc[2 * jn],     aq, &bk4[0]);
                mma_f16(sacc[2 * jn + 1], aq, &bk4[2]);
            }
        }

        float tm0 = -1e30f, tm1 = -1e30f;
#pragma unroll
        for (int i = 0; i < 8; i++) {
            tm0 = fmaxf(tm0, fmaxf(sacc[i][0], sacc[i][1]));
            tm1 = fmaxf(tm1, fmaxf(sacc[i][2], sacc[i][3]));
        }
        tm0 = fmaxf(tm0, __shfl_xor_sync(0xffffffffu, tm0, 1));
        tm0 = fmaxf(tm0, __shfl_xor_sync(0xffffffffu, tm0, 2));
        tm1 = fmaxf(tm1, __shfl_xor_sync(0xffffffffu, tm1, 1));
        tm1 = fmaxf(tm1, __shfl_xor_sync(0xffffffffu, tm1, 2));

        const float mn0 = fmaxf(mr0, tm0), mn1 = fmaxf(mr1, tm1);
        const float al0 = exp2f(mr0 - mn0), al1 = exp2f(mr1 - mn1);
        mr0 = mn0; mr1 = mn1;

        uint32_t phi[8][2];
        float ps0 = 0.f, ps1 = 0.f;
#pragma unroll
        for (int i = 0; i < 8; i++) {
            float p00 = exp2f(sacc[i][0] - mn0);
            float p01 = exp2f(sacc[i][1] - mn0);
            float p10 = exp2f(sacc[i][2] - mn1);
            float p11 = exp2f(sacc[i][3] - mn1);
            ps0 += p00 + p01; ps1 += p10 + p11;
            phi[i][0] = pack_h2(p00, p01);
            phi[i][1] = pack_h2(p10, p11);
        }
        l0 = l0 * al0 + ps0;
        l1 = l1 * al1 + ps1;
        if (al0 != 1.f || al1 != 1.f) {
#pragma unroll
            for (int i = 0; i < 16; i++) {
                oacc[i][0] *= al0; oacc[i][1] *= al0;
                oacc[i][2] *= al1; oacc[i][3] *= al1;
            }
        }

#pragma unroll
        for (int pk = 0; pk < 4; pk++) {
            uint32_t ap[4] = {phi[2 * pk][0], phi[2 * pk][1],
                              phi[2 * pk + 1][0], phi[2 * pk + 1][1]};
#pragma unroll
            for (int jn = 0; jn < 8; jn++) {
                uint32_t bv[4];
                const int vr = jn * 16 + (lid & 7) + ((lid >> 4) & 1) * 8;
                const int vg = pk * 2 + ((lid >> 3) & 1);
                ldsm4(bv, stb + F_V + SWR(vr, vg));
                mma_f16(oacc[2 * jn],     ap, &bv[0]);
                mma_f16(oacc[2 * jn + 1], ap, &bv[2]);
            }
        }
    }

    l0 += __shfl_xor_sync(0xffffffffu, l0, 1);
    l0 += __shfl_xor_sync(0xffffffffu, l0, 2);
    l1 += __shfl_xor_sync(0xffffffffu, l1, 1);
    l1 += __shfl_xor_sync(0xffffffffu, l1, 2);
    const float inv0 = 1.0f / l0, inv1 = 1.0f / l1;

    const int r = lid >> 2, c2 = (lid & 3) * 2;
    const int qg = q0 + wid * 16 + r;
    const size_t row0 = ((size_t)(zb * LQ_) + qg) * D_ + zh * HD_;
    const size_t row1 = row0 + 8 * D_;
#pragma unroll
    for (int jt = 0; jt < 16; jt++) {
        int col = jt * 8 + c2;
        *(uint32_t*)(ct + row0 + col) = pack_h2(oacc[jt][0] * inv0, oacc[jt][1] * inv0);
        *(uint32_t*)(ct + row1 + col) = pack_h2(oacc[jt][2] * inv1, oacc[jt][3] * inv1);
    }
}

// ---------------------------------------------------------------------------
extern "C" void kernel_launch(void* const* d_in, const int* in_sizes, int n_in,
                              void* d_out, int out_size)
{
    const float* x   = (const float*)d_in[0];
    const float* enc = (const float*)d_in[1];
    const float* Wq  = (const float*)d_in[2];
    const float* Wk  = (const float*)d_in[3];
    const float* Wv  = (const float*)d_in[4];
    const float* bq  = (const float*)d_in[5];
    const float* bk  = (const float*)d_in[6];
    const float* bv  = (const float*)d_in[7];
    const float* Wo  = (const float*)d_in[8];
    const float* bo  = (const float*)d_in[9];
    float* out = (float*)d_out;

    __half *xh, *eh, *wqh, *wql, *wk, *wv, *woh, *wol;
    __half *qh, *kh, *vth, *ct;
    cudaGetSymbolAddress((void**)&xh,  g_xh);
    cudaGetSymbolAddress((void**)&eh,  g_eh);
    cudaGetSymbolAddress((void**)&wqh, g_wqhi); cudaGetSymbolAddress((void**)&wql, g_wqlo);
    cudaGetSymbolAddress((void**)&wk,  g_wk);
    cudaGetSymbolAddress((void**)&wv,  g_wv);
    cudaGetSymbolAddress((void**)&woh, g_wohi); cudaGetSymbolAddress((void**)&wol, g_wolo);
    cudaGetSymbolAddress((void**)&qh,  g_qh);   cudaGetSymbolAddress((void**)&kh,  g_kh);
    cudaGetSymbolAddress((void**)&vth, g_vth);  cudaGetSymbolAddress((void**)&ct,  g_ct);

    cudaFuncSetAttribute((const void*)kvf_kernel,   cudaFuncAttributeMaxDynamicSharedMemorySize, KVF_SMEM);
    cudaFuncSetAttribute((const void*)qo_kernel<0>, cudaFuncAttributeMaxDynamicSharedMemorySize, QO_SMEM);
    cudaFuncSetAttribute((const void*)qo_kernel<1>, cudaFuncAttributeMaxDynamicSharedMemorySize, QO_SMEM);
    cudaFuncSetAttribute((const void*)flash_kernel, cudaFuncAttributeMaxDynamicSharedMemorySize, FLASH_SMEM);

    // 1) single prep launch
    prep_kernel<<<dim3(256, 6), 256>>>(x, enc, Wq, Wk, Wv, Wo,
                                       xh, eh, wqh, wql, wk, wv, woh, wol);

    // 2) Q projection (2-pass, 128x64 tiles -> 256 CTAs, pre-scaled)
    qo_kernel<1><<<dim3(8, 32), 256, QO_SMEM>>>(
        xh, wqh, wql, nullptr, qh, bq, QSCALE_);

    // 3) fused K+V projection (shared A tile, 128x128 -> 512 CTAs)
    kvf_kernel<<<dim3(4, 128), 256, KVF_SMEM>>>(eh, wk, wv, kh, vth, bk, bv);

    // 4) fused flash attention (fp16, exp2) -> ctx fp16
    flash_kernel<<<dim3(LQ_ / 64, B_ * H_), 128, FLASH_SMEM>>>(qh, kh, vth, ct);

    // 5) output projection (2-pass, 128x64 tiles -> 256 CTAs) -> fp32 out
    qo_kernel<0><<<dim3(8, 32), 256, QO_SMEM>>>(
        ct, woh, wol, out, nullptr, bo, 1.0f);
}

// round 17
// speedup vs baseline: 1.1129x; 1.1129x over previous
#include <cuda_runtime.h>
#include <cuda_bf16.h>
#include <cuda_fp16.h>
#include <cstdint>
#include <math.h>

#define B_   4
#define LQ_  1024
#define LKV_ 4096
#define D_   512
#define H_   4
#define HD_  128
#define SCALE_ 0.08838834764831845f      // 1/sqrt(128)
#define LOG2E_ 1.4426950408889634f
#define QSCALE_ (SCALE_ * LOG2E_)        // logits emitted in log2 domain

// ---------------------------------------------------------------------------
// Helpers
// ---------------------------------------------------------------------------
__device__ __forceinline__ uint32_t smem_u32(const void* p) {
    uint32_t a;
    asm("{ .reg .u64 t; cvta.to.shared.u64 t, %1; cvt.u32.u64 %0, t; }" : "=r"(a) : "l"(p));
    return a;
}

#define CP_ASYNC16(sa, g) \
    asm volatile("cp.async.cg.shared.global [%0], [%1], 16;" :: "r"(sa), "l"(g))
#define CP_COMMIT() asm volatile("cp.async.commit_group;" ::: "memory")
#define CP_WAIT(n)  asm volatile("cp.async.wait_group %0;" :: "n"(n) : "memory")

__device__ __forceinline__ void ldsm4(uint32_t* r, uint32_t a) {
    asm volatile("ldmatrix.sync.aligned.m8n8.x4.shared.b16 {%0,%1,%2,%3}, [%4];"
                 : "=r"(r[0]), "=r"(r[1]), "=r"(r[2]), "=r"(r[3]) : "r"(a));
}
__device__ __forceinline__ void mma_f16(float* c, const uint32_t* a, const uint32_t* b) {
    asm volatile("mma.sync.aligned.m16n8k16.row.col.f32.f16.f16.f32 "
                 "{%0,%1,%2,%3}, {%4,%5,%6,%7}, {%8,%9}, {%0,%1,%2,%3};"
                 : "+f"(c[0]), "+f"(c[1]), "+f"(c[2]), "+f"(c[3])
                 : "r"(a[0]), "r"(a[1]), "r"(a[2]), "r"(a[3]), "r"(b[0]), "r"(b[1]));
}
__device__ __forceinline__ uint32_t pack_h2(float a, float b) {
    __half2 v = __floats2half2_rn(a, b);
    return *(uint32_t*)&v;
}

// 128B-row swizzle (8 granules of 16B per row), conflict-free for ldsm
#define SWR(r, g) ((uint32_t)(r) * 128 + ((uint32_t)((g) ^ ((r) & 7)) << 4))
// 256B-row swizzle (flash Q/K tiles)
#define SWQ(r, g) ((uint32_t)(r) * 256 + ((uint32_t)((g) ^ ((r) & 15)) << 4))

// ---------------------------------------------------------------------------
// Device scratch (allocation-free)
// ---------------------------------------------------------------------------
#define NX  ((size_t)B_ * LQ_ * D_)
#define NE  ((size_t)B_ * LKV_ * D_)
#define NW  ((size_t)D_ * D_)

__device__ __half g_xh[NX];
__device__ __half g_eh[NE];
__device__ __half g_wqhi[NW], g_wqlo[NW];
__device__ __half g_wk[NW];
__device__ __half g_wv[NW];
__device__ __half g_wohi[NW], g_wolo[NW];
__device__ __half g_qh[NX];
__device__ __half g_kh[NE];
__device__ __half g_vth[NE];           // transposed [b][h*HD+d][lkv]
__device__ __half g_ct[NX];

// ---------------------------------------------------------------------------
// Single prep kernel: y selects task
// ---------------------------------------------------------------------------
__global__ __launch_bounds__(256) void prep_kernel(
    const float* __restrict__ x, const float* __restrict__ enc,
    const float* __restrict__ Wq, const float* __restrict__ Wk,
    const float* __restrict__ Wv, const float* __restrict__ Wo,
    __half* __restrict__ xh, __half* __restrict__ eh,
    __half* __restrict__ wqh, __half* __restrict__ wql,
    __half* __restrict__ wk, __half* __restrict__ wv,
    __half* __restrict__ woh, __half* __restrict__ wol)
{
    const int which = blockIdx.y;
    const int stride = gridDim.x * blockDim.x;
    const int tid0 = blockIdx.x * blockDim.x + threadIdx.x;
    if (which <= 1 || which == 3 || which == 4) {
        const float* in = (which == 0) ? x : (which == 1) ? enc : (which == 3) ? Wk : Wv;
        __half* outp    = (which == 0) ? xh : (which == 1) ? eh : (which == 3) ? wk : wv;
        const int n4    = (which == 0) ? (int)(NX / 4) : (which == 1) ? (int)(NE / 4) : (int)(NW / 4);
        for (int i = tid0; i < n4; i += stride) {
            float4 v = ((const float4*)in)[i];
            ((uint2*)outp)[i] = make_uint2(pack_h2(v.x, v.y), pack_h2(v.z, v.w));
        }
    } else {
        const float* in = (which == 2) ? Wq : Wo;
        __half* hi = (which == 2) ? wqh : woh;
        __half* lo = (which == 2) ? wql : wol;
        const int n4 = (int)(NW / 4);
        for (int i = tid0; i < n4; i += stride) {
            float4 v = ((const float4*)in)[i];
            float f[4] = {v.x, v.y, v.z, v.w};
            float h[4], l[4];
#pragma unroll
            for (int j = 0; j < 4; j++) {
                h[j] = __half2float(__float2half_rn(f[j]));
                l[j] = f[j] - h[j];
            }
            ((uint2*)hi)[i] = make_uint2(pack_h2(h[0], h[1]), pack_h2(h[2], h[3]));
            ((uint2*)lo)[i] = make_uint2(pack_h2(l[0], l[1]), pack_h2(l[2], l[3]));
        }
    }
}

// ---------------------------------------------------------------------------
// Merged K+V projection (R14-proven): 1-pass fp16, K-chunk 64, 3-stage ring,
// no trailing barrier. z: 0 = K (row-major fp16), 1 = V (transposed fp16).
// CTA tile 128x128, warp tile 64x32.
// ---------------------------------------------------------------------------
#define OFF_A  0
#define OFF_BH 16384
#define KV_SMEM 98304   // 3 stages x 32768

__global__ __launch_bounds__(256) void kv_kernel(
    const __half* __restrict__ A,
    const __half* __restrict__ Wk_, const __half* __restrict__ Wv_,
    __half* __restrict__ kh, __half* __restrict__ vth,
    const float* __restrict__ bk, const float* __restrict__ bv)
{
    extern __shared__ char smem[];
    const uint32_t sb = smem_u32(smem);
    const int t = threadIdx.x, wid = t >> 5, lid = t & 31;
    const int wm = wid & 1, wn = wid >> 1;
    const int m0 = blockIdx.y * 128, n0 = blockIdx.x * 128;
    const int zz = blockIdx.z;

    const __half* Bsel = zz ? Wv_ : Wk_;
    const float* bsel  = zz ? bv : bk;

    const __half* Ab  = A + (size_t)m0 * D_;
    const __half* Bbh = Bsel + (size_t)n0 * D_;

    float acc[4][4][4];
#pragma unroll
    for (int i = 0; i < 4; i++)
#pragma unroll
        for (int j = 0; j < 4; j++)
#pragma unroll
            for (int r = 0; r < 4; r++) acc[i][j][r] = 0.f;

    const int nch = D_ >> 6;

    auto load_stage = [&](int c) {
        const int k0 = c << 6;
        const uint32_t sbase = sb + (c % 3) * 32768;
#pragma unroll
        for (int i = 0; i < 4; i++) {
            int idx = t + i * 256;
            int r = idx >> 3, s = idx & 7;
            uint32_t so = SWR(r, s);
            size_t oa = (size_t)r * D_ + k0 + s * 8;
            CP_ASYNC16(sbase + OFF_A + so, Ab + oa);
            CP_ASYNC16(sbase + OFF_BH + so, Bbh + oa);
        }
        CP_COMMIT();
    };

    load_stage(0);

    for (int c = 0; c < nch; c++) {
        if (c + 1 < nch) { load_stage(c + 1); CP_WAIT(1); }
        else             { CP_WAIT(0); }
        __syncthreads();

        const uint32_t sbase = sb + (c % 3) * 32768;
#pragma unroll
        for (int ks = 0; ks < 4; ks++) {
            uint32_t ah[4][4], bh[2][4];
            const int ar = wm * 64 + (lid & 15);
            const int ag = ks * 2 + (lid >> 4);
#pragma unroll
            for (int im = 0; im < 4; im++)
                ldsm4(ah[im], sbase + OFF_A + SWR(ar + im * 16, ag));
            const int br = wn * 32 + (lid & 7) + ((lid >> 4) & 1) * 8;
            const int bg = ks * 2 + ((lid >> 3) & 1);
#pragma unroll
            for (int g = 0; g < 2; g++)
                ldsm4(bh[g], sbase + OFF_BH + SWR(br + g * 16, bg));
#pragma unroll
            for (int im = 0; im < 4; im++)
#pragma unroll
                for (int in = 0; in < 4; in++)
                    mma_f16(acc[im][in], ah[im], &bh[in >> 1][(in & 1) * 2]);
        }
        // 3-stage ring: no trailing barrier needed
    }

    const int group = lid >> 2, tid4 = lid & 3;

#pragma unroll
    for (int im = 0; im < 4; im++)
#pragma unroll
        for (int in = 0; in < 4; in++) {
            int row = m0 + wm * 64 + im * 16 + group;
            int col = n0 + wn * 32 + in * 8 + tid4 * 2;
#pragma unroll
            for (int rr = 0; rr < 2; rr++) {
                int m = row + rr * 8;
                float v0 = acc[im][in][rr * 2]     + bsel[col];
                float v1 = acc[im][in][rr * 2 + 1] + bsel[col + 1];
                if (zz == 0) {
                    *(uint32_t*)(kh + (size_t)m * D_ + col) = pack_h2(v0, v1);
                } else {
                    int bb = m >> 12, kv = m & (LKV_ - 1);
                    vth[((size_t)(bb * D_ + col)) * LKV_ + kv]     = __float2half_rn(v0);
                    vth[((size_t)(bb * D_ + col + 1)) * LKV_ + kv] = __float2half_rn(v1);
                }
            }
        }
}

// ---------------------------------------------------------------------------
// Q / O projection (R14-proven): 2-pass fp16, CTA tile 128x64 (-> 256 CTAs),
// warp 64x16, K-chunk 64, 2-stage. MODE 0: fp32 out (+bias). MODE 1: fp16 out
// ((v+bias)*scale). Epilogue stores vectorized.
// ---------------------------------------------------------------------------
#define QO_A   0
#define QO_BH  16384
#define QO_BL  24576
#define QO_STG 32768
#define QO_SMEM 65536

template <int MODE>
__global__ __launch_bounds__(256) void qo_kernel(
    const __half* __restrict__ A,
    const __half* __restrict__ Bh, const __half* __restrict__ Bl,
    float* __restrict__ Cf, __half* __restrict__ Ch,
    const float* __restrict__ bias, float scale)
{
    extern __shared__ char smem[];
    const uint32_t sb = smem_u32(smem);
    const int t = threadIdx.x, wid = t >> 5, lid = t & 31;
    const int wm = wid & 1, wn = wid >> 1;
    const int m0 = blockIdx.y * 128, n0 = blockIdx.x * 64;

    const __half* Ab  = A  + (size_t)m0 * D_;
    const __half* Bbh = Bh + (size_t)n0 * D_;
    const __half* Bbl = Bl + (size_t)n0 * D_;

    float acc[4][2][4];
#pragma unroll
    for (int i = 0; i < 4; i++)
#pragma unroll
        for (int j = 0; j < 2; j++)
#pragma unroll
            for (int r = 0; r < 4; r++) acc[i][j][r] = 0.f;

    const int nch = D_ >> 6;

    auto load_stage = [&](int c) {
        const int k0 = c << 6;
        const uint32_t sbase = sb + (c & 1) * QO_STG;
#pragma unroll
        for (int i = 0; i < 4; i++) {
            int idx = t + i * 256;
            int r = idx >> 3, s = idx & 7;
            CP_ASYNC16(sbase + QO_A + SWR(r, s), Ab + (size_t)r * D_ + k0 + s * 8);
        }
#pragma unroll
        for (int i = 0; i < 2; i++) {
            int idx = t + i * 256;
            int r = idx >> 3, s = idx & 7;
            size_t ob = (size_t)r * D_ + k0 + s * 8;
            uint32_t so = SWR(r, s);
            CP_ASYNC16(sbase + QO_BH + so, Bbh + ob);
            CP_ASYNC16(sbase + QO_BL + so, Bbl + ob);
        }
        CP_COMMIT();
    };

    load_stage(0);

    for (int c = 0; c < nch; c++) {
        if (c + 1 < nch) { load_stage(c + 1); CP_WAIT(1); }
        else             { CP_WAIT(0); }
        __syncthreads();

        const uint32_t sbase = sb + (c & 1) * QO_STG;
#pragma unroll
        for (int ks = 0; ks < 4; ks++) {
            uint32_t ah[4][4], bh[4], bl[4];
            const int ar = wm * 64 + (lid & 15);
            const int ag = ks * 2 + (lid >> 4);
#pragma unroll
            for (int im = 0; im < 4; im++)
                ldsm4(ah[im], sbase + QO_A + SWR(ar + im * 16, ag));
            const int br = wn * 16 + (lid & 7) + ((lid >> 4) & 1) * 8;
            const int bg = ks * 2 + ((lid >> 3) & 1);
            uint32_t off = SWR(br, bg);
            ldsm4(bh, sbase + QO_BH + off);
            ldsm4(bl, sbase + QO_BL + off);
#pragma unroll
            for (int im = 0; im < 4; im++)
#pragma unroll
                for (int in = 0; in < 2; in++) {
                    mma_f16(acc[im][in], ah[im], &bh[in * 2]);
                    mma_f16(acc[im][in], ah[im], &bl[in * 2]);
                }
        }
        __syncthreads();
    }

    const int group = lid >> 2, tid4 = lid & 3;
#pragma unroll
    for (int im = 0; im < 4; im++)
#pragma unroll
        for (int in = 0; in < 2; in++) {
            int row = m0 + wm * 64 + im * 16 + group;
            int col = n0 + wn * 16 + in * 8 + tid4 * 2;
#pragma unroll
            for (int rr = 0; rr < 2; rr++) {
                float v0 = acc[im][in][rr * 2]     + bias[col];
                float v1 = acc[im][in][rr * 2 + 1] + bias[col + 1];
                if (MODE == 0) {
                    *(float2*)(Cf + (size_t)(row + rr * 8) * D_ + col) = make_float2(v0, v1);
                } else {
                    *(uint32_t*)(Ch + (size_t)(row + rr * 8) * D_ + col) = pack_h2(v0 * scale, v1 * scale);
                }
            }
        }
}

// ---------------------------------------------------------------------------
// Flash attention (R11/R14-proven): fp16 single-pass, exp2 softmax,
// Q-tile 64, 128 threads, 3-stage KV ring, single barrier per iteration.
// ---------------------------------------------------------------------------
#define F_Q    0
#define F_ST   16384
#define F_STSZ 32768
#define F_K    0
#define F_V    16384
#define FLASH_SMEM (F_ST + 3 * F_STSZ)   // 114688

__global__ __launch_bounds__(128, 2) void flash_kernel(
    const __half* __restrict__ q, const __half* __restrict__ k,
    const __half* __restrict__ vt, __half* __restrict__ ct)
{
    extern __shared__ char smem[];
    const uint32_t sb = smem_u32(smem);
    const int t = threadIdx.x, wid = t >> 5, lid = t & 31;
    const int z = blockIdx.y, zb = z >> 2, zh = z & 3;
    const int q0 = blockIdx.x * 64;

#pragma unroll
    for (int i = 0; i < 8; i++) {
        int idx = t + i * 128;
        int r = idx >> 4, g = idx & 15;
        const __half* gp = q + ((size_t)(zb * LQ_ + q0 + r)) * D_ + zh * HD_ + g * 8;
        CP_ASYNC16(sb + F_Q + SWQ(r, g), gp);
    }
    CP_COMMIT();

    auto load_kv = [&](int kt2) {
        const int kv0 = kt2 * 64;
        const uint32_t stb = sb + F_ST + (kt2 % 3) * F_STSZ;
#pragma unroll
        for (int i = 0; i < 8; i++) {
            int idx = t + i * 128;
            int r = idx >> 4, g = idx & 15;
            const __half* gp = k + ((size_t)(zb * LKV_ + kv0 + r)) * D_ + zh * HD_ + g * 8;
            CP_ASYNC16(stb + F_K + SWQ(r, g), gp);
        }
#pragma unroll
        for (int i = 0; i < 8; i++) {
            int idx = t + i * 128;
            int r = idx >> 3, g = idx & 7;
            const __half* gp = vt + ((size_t)(zb * D_ + zh * HD_ + r)) * LKV_ + kv0 + g * 8;
            CP_ASYNC16(stb + F_V + SWR(r, g), gp);
        }
        CP_COMMIT();
    };

    load_kv(0);

    float oacc[16][4];
#pragma unroll
    for (int i = 0; i < 16; i++)
#pragma unroll
        for (int j = 0; j < 4; j++) oacc[i][j] = 0.f;
    float mr0 = -1e30f, mr1 = -1e30f, l0 = 0.f, l1 = 0.f;

    for (int kt = 0; kt < LKV_ / 64; kt++) {
        if (kt + 1 < LKV_ / 64) { load_kv(kt + 1); CP_WAIT(1); }
        else                    { CP_WAIT(0); }
        __syncthreads();
        const uint32_t stb = sb + F_ST + (kt % 3) * F_STSZ;

        float sacc[8][4];
#pragma unroll
        for (int i = 0; i < 8; i++)
#pragma unroll
            for (int j = 0; j < 4; j++) sacc[i][j] = 0.f;

#pragma unroll
        for (int ks = 0; ks < 8; ks++) {
            uint32_t aq[4];
            const int ar = wid * 16 + (lid & 15);
            const int ag = ks * 2 + (lid >> 4);
            ldsm4(aq, sb + F_Q + SWQ(ar, ag));
#pragma unroll
            for (int jn = 0; jn < 4; jn++) {
                uint32_t bk4[4];
                const int br = jn * 16 + (lid & 7) + ((lid >> 4) & 1) * 8;
                const int bg = ks * 2 + ((lid >> 3) & 1);
                ldsm4(bk4, stb + F_K + SWQ(br, bg));
                mma_f16(sacc[2 * jn],     aq, &bk4[0]);
                mma_f16(sacc[2 * jn + 1], aq, &bk4[2]);
            }
        }

        float tm0 = -1e30f, tm1 = -1e30f;
#pragma unroll
        for (int i = 0; i < 8; i++) {
            tm0 = fmaxf(tm0, fmaxf(sacc[i][0], sacc[i][1]));
            tm1 = fmaxf(tm1, fmaxf(sacc[i][2], sacc[i][3]));
        }
        tm0 = fmaxf(tm0, __shfl_xor_sync(0xffffffffu, tm0, 1));
        tm0 = fmaxf(tm0, __shfl_xor_sync(0xffffffffu, tm0, 2));
        tm1 = fmaxf(tm1, __shfl_xor_sync(0xffffffffu, tm1, 1));
        tm1 = fmaxf(tm1, __shfl_xor_sync(0xffffffffu, tm1, 2));

        const float mn0 = fmaxf(mr0, tm0), mn1 = fmaxf(mr1, tm1);
        const float al0 = exp2f(mr0 - mn0), al1 = exp2f(mr1 - mn1);
        mr0 = mn0; mr1 = mn1;

        uint32_t phi[8][2];
        float ps0 = 0.f, ps1 = 0.f;
#pragma unroll
        for (int i = 0; i < 8; i++) {
            float p00 = exp2f(sacc[i][0] - mn0);
            float p01 = exp2f(sacc[i][1] - mn0);
            float p10 = exp2f(sacc[i][2] - mn1);
            float p11 = exp2f(sacc[i][3] - mn1);
            ps0 += p00 + p01; ps1 += p10 + p11;
            phi[i][0] = pack_h2(p00, p01);
            phi[i][1] = pack_h2(p10, p11);
        }
        l0 = l0 * al0 + ps0;
        l1 = l1 * al1 + ps1;
        if (al0 != 1.f || al1 != 1.f) {
#pragma unroll
            for (int i = 0; i < 16; i++) {
                oacc[i][0] *= al0; oacc[i][1] *= al0;
                oacc[i][2] *= al1; oacc[i][3] *= al1;
            }
        }

#pragma unroll
        for (int pk = 0; pk < 4; pk++) {
            uint32_t ap[4] = {phi[2 * pk][0], phi[2 * pk][1],
                              phi[2 * pk + 1][0], phi[2 * pk + 1][1]};
#pragma unroll
            for (int jn = 0; jn < 8; jn++) {
                uint32_t bv[4];
                const int vr = jn * 16 + (lid & 7) + ((lid >> 4) & 1) * 8;
                const int vg = pk * 2 + ((lid >> 3) & 1);
                ldsm4(bv, stb + F_V + SWR(vr, vg));
                mma_f16(oacc[2 * jn],     ap, &bv[0]);
                mma_f16(oacc[2 * jn + 1], ap, &bv[2]);
            }
        }
    }

    l0 += __shfl_xor_sync(0xffffffffu, l0, 1);
    l0 += __shfl_xor_sync(0xffffffffu, l0, 2);
    l1 += __shfl_xor_sync(0xffffffffu, l1, 1);
    l1 += __shfl_xor_sync(0xffffffffu, l1, 2);
    const float inv0 = 1.0f / l0, inv1 = 1.0f / l1;

    const int r = lid >> 2, c2 = (lid & 3) * 2;
    const int qg = q0 + wid * 16 + r;
    const size_t row0 = ((size_t)(zb * LQ_) + qg) * D_ + zh * HD_;
    const size_t row1 = row0 + 8 * D_;
#pragma unroll
    for (int jt = 0; jt < 16; jt++) {
        int col = jt * 8 + c2;
        *(uint32_t*)(ct + row0 + col) = pack_h2(oacc[jt][0] * inv0, oacc[jt][1] * inv0);
        *(uint32_t*)(ct + row1 + col) = pack_h2(oacc[jt][2] * inv1, oacc[jt][3] * inv1);
    }
}

// ---------------------------------------------------------------------------
extern "C" void kernel_launch(void* const* d_in, const int* in_sizes, int n_in,
                              void* d_out, int out_size)
{
    const float* x   = (const float*)d_in[0];
    const float* enc = (const float*)d_in[1];
    const float* Wq  = (const float*)d_in[2];
    const float* Wk  = (const float*)d_in[3];
    const float* Wv  = (const float*)d_in[4];
    const float* bq  = (const float*)d_in[5];
    const float* bk  = (const float*)d_in[6];
    const float* bv  = (const float*)d_in[7];
    const float* Wo  = (const float*)d_in[8];
    const float* bo  = (const float*)d_in[9];
    float* out = (float*)d_out;

    __half *xh, *eh, *wqh, *wql, *wk, *wv, *woh, *wol;
    __half *qh, *kh, *vth, *ct;
    cudaGetSymbolAddress((void**)&xh,  g_xh);
    cudaGetSymbolAddress((void**)&eh,  g_eh);
    cudaGetSymbolAddress((void**)&wqh, g_wqhi); cudaGetSymbolAddress((void**)&wql, g_wqlo);
    cudaGetSymbolAddress((void**)&wk,  g_wk);
    cudaGetSymbolAddress((void**)&wv,  g_wv);
    cudaGetSymbolAddress((void**)&woh, g_wohi); cudaGetSymbolAddress((void**)&wol, g_wolo);
    cudaGetSymbolAddress((void**)&qh,  g_qh);   cudaGetSymbolAddress((void**)&kh,  g_kh);
    cudaGetSymbolAddress((void**)&vth, g_vth);  cudaGetSymbolAddress((void**)&ct,  g_ct);

    cudaFuncSetAttribute((const void*)kv_kernel,    cudaFuncAttributeMaxDynamicSharedMemorySize, KV_SMEM);
    cudaFuncSetAttribute((const void*)qo_kernel<0>, cudaFuncAttributeMaxDynamicSharedMemorySize, QO_SMEM);
    cudaFuncSetAttribute((const void*)qo_kernel<1>, cudaFuncAttributeMaxDynamicSharedMemorySize, QO_SMEM);
    cudaFuncSetAttribute((const void*)flash_kernel, cudaFuncAttributeMaxDynamicSharedMemorySize, FLASH_SMEM);

    // 1) single prep launch
    prep_kernel<<<dim3(256, 6), 256>>>(x, enc, Wq, Wk, Wv, Wo,
                                       xh, eh, wqh, wql, wk, wv, woh, wol);

    // 2) Q projection (2-pass, 128x64 tiles -> 256 CTAs, pre-scaled)
    qo_kernel<1><<<dim3(8, 32), 256, QO_SMEM>>>(
        xh, wqh, wql, nullptr, qh, bq, QSCALE_);

    // 3) merged K+V projections (1-pass, 128x128 tiles, z: 0=K, 1=V transposed)
    kv_kernel<<<dim3(4, 128, 2), 256, KV_SMEM>>>(eh, wk, wv, kh, vth, bk, bv);

    // 4) fused flash attention (fp16, exp2) -> ctx fp16
    flash_kernel<<<dim3(LQ_ / 64, B_ * H_), 128, FLASH_SMEM>>>(qh, kh, vth, ct);

    // 5) output projection (2-pass, 128x64 tiles -> 256 CTAs) -> fp32 out
    qo_kernel<0><<<dim3(8, 32), 256, QO_SMEM>>>(
        ct, woh, wol, out, nullptr, bo, 1.0f);
}